// round 2
// baseline (speedup 1.0000x reference)
#include <cuda_runtime.h>

#define NN 50000
#define DD 128
#define EE 800000

// ---- scratch (__device__ globals: allocation-free) ----
__device__ int   g_degcol[NN];     // degree over col (for norm)
__device__ int   g_cntrow[NN];     // degree over row (for CSR)
__device__ int   g_off[NN + 1];    // CSR row offsets
__device__ int   g_cursor[NN];     // scatter cursors
__device__ int   g_scol[EE];       // edges sorted by row: col ids
__device__ float g_dis[NN];        // deg_col^-0.5 (0 if deg==0)
__device__ unsigned int g_maxbits; // ordered-float max of x
__device__ float2 g_ppM;           // (pp, M = pp*max(x))

// ordered-float encoding for atomicMax on signed floats
__device__ __forceinline__ unsigned int ford(float f) {
    unsigned int b = __float_as_uint(f);
    return (b & 0x80000000u) ? ~b : (b | 0x80000000u);
}
__device__ __forceinline__ float funord(unsigned int u) {
    unsigned int b = (u & 0x80000000u) ? (u & 0x7FFFFFFFu) : ~u;
    return __uint_as_float(b);
}

__global__ void k_init() {
    int i = blockIdx.x * blockDim.x + threadIdx.x;
    if (i < NN) { g_degcol[i] = 0; g_cntrow[i] = 0; }
    if (i == 0) g_maxbits = ford(-3.402823466e38f);
}

__global__ void k_count(const int* __restrict__ ei) {
    int e = blockIdx.x * blockDim.x + threadIdx.x;
    if (e < EE) {
        int r = ei[e];
        int c = ei[EE + e];
        atomicAdd(&g_cntrow[r], 1);
        atomicAdd(&g_degcol[c], 1);
    }
}

__global__ void k_max(const float* __restrict__ x) {
    float m = -3.402823466e38f;
    const float4* x4 = (const float4*)x;
    const int n4 = (NN * DD) / 4;
    for (int i = blockIdx.x * blockDim.x + threadIdx.x; i < n4;
         i += gridDim.x * blockDim.x) {
        float4 v = x4[i];
        m = fmaxf(m, fmaxf(fmaxf(v.x, v.y), fmaxf(v.z, v.w)));
    }
#pragma unroll
    for (int o = 16; o; o >>= 1) m = fmaxf(m, __shfl_xor_sync(~0u, m, o));
    __shared__ float sm[32];
    int lane = threadIdx.x & 31, w = threadIdx.x >> 5;
    if (lane == 0) sm[w] = m;
    __syncthreads();
    if (w == 0) {
        m = (lane < (int)(blockDim.x >> 5)) ? sm[lane] : -3.402823466e38f;
#pragma unroll
        for (int o = 16; o; o >>= 1) m = fmaxf(m, __shfl_xor_sync(~0u, m, o));
        if (lane == 0) atomicMax(&g_maxbits, ford(m));
    }
}

__global__ void k_dis(const float* __restrict__ p) {
    int i = blockIdx.x * blockDim.x + threadIdx.x;
    if (i < NN) {
        int dg = g_degcol[i];
        g_dis[i] = (dg > 0) ? rsqrtf((float)dg) : 0.0f;
    }
    if (i == 0) {
        float pp = 2.0f / (1.0f + __expf(-p[0]));
        float M = pp * funord(g_maxbits);
        g_ppM = make_float2(pp, M);
    }
}

// single-block exclusive scan of g_cntrow -> g_off, g_cursor
__global__ void k_scan() {
    const int C = (NN + 1023) / 1024;  // 49 elems per thread
    __shared__ int part[1024];
    int tid = threadIdx.x;
    int base = tid * C;
    int s = 0;
    for (int k = 0; k < C; k++) {
        int i = base + k;
        s += (i < NN) ? g_cntrow[i] : 0;
    }
    part[tid] = s;
    __syncthreads();
    for (int off = 1; off < 1024; off <<= 1) {
        int t = (tid >= off) ? part[tid - off] : 0;
        __syncthreads();
        part[tid] += t;
        __syncthreads();
    }
    int run = part[tid] - s;  // exclusive prefix of this chunk
    for (int k = 0; k < C; k++) {
        int i = base + k;
        if (i < NN) {
            g_off[i] = run;
            g_cursor[i] = run;
            run += g_cntrow[i];
        }
    }
    if (tid == 1023) g_off[NN] = run;
}

__global__ void k_scatter(const int* __restrict__ ei) {
    int e = blockIdx.x * blockDim.x + threadIdx.x;
    if (e < EE) {
        int r = ei[e];
        int c = ei[EE + e];
        int pos = atomicAdd(&g_cursor[r], 1);
        g_scol[pos] = c;
    }
}

// one block (128 threads) per node r; thread d handles feature d
__global__ void __launch_bounds__(128) k_main(const float* __restrict__ x,
                                              const float* __restrict__ eps,
                                              float* __restrict__ out) {
    const int r = blockIdx.x;
    const int d = threadIdx.x;
    const int start = g_off[r];
    const int end   = g_off[r + 1];
    const float2 ppM = g_ppM;
    const float pp = ppM.x, M = ppM.y;

    __shared__ int   s_c[128];
    __shared__ float s_w[128];

    float num = 0.0f, den = 0.0f;

    for (int base = start; base < end; base += 128) {
        int j = base + d;
        if (j < end) {
            int c = g_scol[j];
            s_c[d] = c;
            s_w[d] = g_dis[c];
        }
        __syncthreads();
        int m = end - base;
        if (m > 128) m = 128;
        int k = 0;
        for (; k + 4 <= m; k += 4) {
            int   c0 = s_c[k],     c1 = s_c[k + 1], c2 = s_c[k + 2], c3 = s_c[k + 3];
            float w0 = s_w[k],     w1 = s_w[k + 1], w2 = s_w[k + 2], w3 = s_w[k + 3];
            float t0 = __ldg(&x[c0 * DD + d]);
            float t1 = __ldg(&x[c1 * DD + d]);
            float t2 = __ldg(&x[c2 * DD + d]);
            float t3 = __ldg(&x[c3 * DD + d]);
            float s0 = __expf(fmaf(pp, t0, -M));
            float s1 = __expf(fmaf(pp, t1, -M));
            float s2 = __expf(fmaf(pp, t2, -M));
            float s3 = __expf(fmaf(pp, t3, -M));
            den = fmaf(s0, w0, den); num = fmaf(s0 * t0, w0, num);
            den = fmaf(s1, w1, den); num = fmaf(s1 * t1, w1, num);
            den = fmaf(s2, w2, den); num = fmaf(s2 * t2, w2, num);
            den = fmaf(s3, w3, den); num = fmaf(s3 * t3, w3, num);
        }
        for (; k < m; k++) {
            int   c = s_c[k];
            float w = s_w[k];
            float t = __ldg(&x[c * DD + d]);
            float s = __expf(fmaf(pp, t, -M));
            den = fmaf(s, w, den);
            num = fmaf(s * t, w, num);
        }
        __syncthreads();
    }

    float dis_r = g_dis[r];
    float xv = x[r * DD + d];
    float o = __fdividef(dis_r * num, fmaf(dis_r, den, 1e-6f)) + (1.0f + eps[0]) * xv;
    out[r * DD + d] = o;
}

extern "C" void kernel_launch(void* const* d_in, const int* in_sizes, int n_in,
                              void* d_out, int out_size) {
    const float* x   = (const float*)d_in[0];
    const int*   ei  = (const int*)d_in[1];
    const float* eps = (const float*)d_in[2];
    const float* p   = (const float*)d_in[3];
    float* out = (float*)d_out;

    k_init   <<<(NN + 255) / 256, 256>>>();
    k_count  <<<(EE + 255) / 256, 256>>>(ei);
    k_max    <<<512, 256>>>(x);
    k_dis    <<<(NN + 255) / 256, 256>>>(p);
    k_scan   <<<1, 1024>>>();
    k_scatter<<<(EE + 255) / 256, 256>>>(ei);
    k_main   <<<NN, 128>>>(x, eps, out);
}